// round 11
// baseline (speedup 1.0000x reference)
#include <cuda_runtime.h>
#include <cuda_fp16.h>
#include <cstdint>

#define N_NODES 100000
#define N_EDGES 1250000
#define D 64
#define NPB 64  // nodes per block in the fused GEMM

typedef unsigned long long ull;

#define PACK_F32X2(out, lo, hi) \
    asm("mov.b64 %0, {%1, %2};" : "=l"(out) : "f"(lo), "f"(hi))
#define UNPACK_F32X2(lo, hi, in) \
    asm("mov.b64 {%0, %1}, %2;" : "=f"(lo), "=f"(hi) : "l"(in))
#define FMA_F32X2(d, a, b, c) \
    asm("fma.rn.f32x2 %0, %1, %2, %3;" : "=l"(d) : "l"(a), "l"(b), "l"(c))
#define TANH_APPROX(y, x) \
    asm("tanh.approx.f32 %0, %1;" : "=f"(y) : "f"(x))

// fp16 scratch (static device memory: allowed, no allocation)
// Two aggregation buffers (split by edge parity) to halve the fp16
// accumulation-rounding chain; combined in fp32 in the GEMM.
__device__ __half g_aggr[2 * N_NODES * D];  // 25.6 MB
__device__ __half g_xh[N_NODES * D];        // 12.8 MB fp16 copy of x

// ---------------------------------------------------------------------------
// Prepass: x (f32) -> g_xh (fp16). 8 floats per thread.
// ---------------------------------------------------------------------------
__global__ void cvt_x_kernel(const float* __restrict__ x) {
    int i = blockIdx.x * blockDim.x + threadIdx.x;   // group of 8 floats
    if (i >= N_NODES * D / 8) return;
    const float4* xp = reinterpret_cast<const float4*>(x) + i * 2;
    float4 v0 = xp[0], v1 = xp[1];
    __half2 h[4];
    h[0] = __float22half2_rn(make_float2(v0.x, v0.y));
    h[1] = __float22half2_rn(make_float2(v0.z, v0.w));
    h[2] = __float22half2_rn(make_float2(v1.x, v1.y));
    h[3] = __float22half2_rn(make_float2(v1.z, v1.w));
    *(reinterpret_cast<uint4*>(g_xh) + i) = *reinterpret_cast<uint4*>(h);
}

// ---------------------------------------------------------------------------
// Scatter: 8 threads/edge; each loads 8 halves of x_h[src] (one LDG.128) and
// does one red.global.add.noftz.v4.f16x2 into the parity-selected aggr buffer
// (one RED.128). Runtime probe of int64 vs int32 edge_index.
// ---------------------------------------------------------------------------
__global__ void scatter_kernel(const int* __restrict__ e32) {
    int t = blockIdx.x * blockDim.x + threadIdx.x;
    int e = t >> 3;
    if (e >= N_EDGES) return;
    int c = (t & 7) << 3;   // half offset within row (0,8,...,56)

    bool is64 = (e32[1] == 0) && (e32[3] == 0) && (e32[5] == 0) && (e32[7] == 0);

    int src, dst;
    if (is64) {
        src = e32[2 * e];
        dst = e32[2 * (N_EDGES + e)];
    } else {
        src = e32[e];
        dst = e32[N_EDGES + e];
    }

    uint4 v = *reinterpret_cast<const uint4*>(g_xh + (long long)src * D + c);
    // parity split: even edges -> buffer 0, odd edges -> buffer 1
    __half* p = g_aggr + ((long long)(e & 1) * N_NODES + dst) * D + c;
    asm volatile("red.global.add.noftz.v4.f16x2 [%0], {%1,%2,%3,%4};"
                 :: "l"(p), "r"(v.x), "r"(v.y), "r"(v.z), "r"(v.w)
                 : "memory");
}

// ---------------------------------------------------------------------------
// Fused GEMM: out = tanh( [aggr | x] @ [W_l ; W_r] + b ) per node.
// aggr = f32(aggr0) + f32(aggr1); all math fp32 (packed fma.rn.f32x2).
// Block: 256 threads, NPB=64 nodes; thread (tx, ng) computes cols
// [4tx,4tx+4) of nodes 4ng..4ng+3.
// ---------------------------------------------------------------------------
__global__ void fused_gemm_kernel(const float* __restrict__ x,
                                  const float* __restrict__ Wl,
                                  const float* __restrict__ bl,
                                  const float* __restrict__ Wr,
                                  float* __restrict__ out) {
    extern __shared__ float sm[];
    float* sW  = sm;                 // [128][64]: rows 0..63 = W_l, 64..127 = W_r
    float* sAX = sm + 128 * 64;      // [NPB][128]: cols 0..63 = aggr, 64..127 = x
    float* sB  = sAX + NPB * 128;    // [64]

    int tid = threadIdx.x;
    int node0 = blockIdx.x * NPB;

    // --- stage weights ---
    float4* sW4 = reinterpret_cast<float4*>(sW);
    const float4* Wl4 = reinterpret_cast<const float4*>(Wl);
    const float4* Wr4 = reinterpret_cast<const float4*>(Wr);
#pragma unroll
    for (int i = 0; i < 4; i++) {
        int idx = tid + i * 256;
        sW4[idx]        = Wl4[idx];
        sW4[1024 + idx] = Wr4[idx];
    }
    if (tid < 64) sB[tid] = bl[tid];

    // --- stage aggr = f32(buf0) + f32(buf1): NPB nodes * 16 groups of 4 ---
    for (int i = tid; i < NPB * 16; i += 256) {
        int n = i >> 4, c = i & 15;
        int node = node0 + n;
        float4 v = make_float4(0.f, 0.f, 0.f, 0.f);
        if (node < N_NODES) {
            long long off = (long long)node * D + c * 4;
            uint2 ha = *reinterpret_cast<const uint2*>(g_aggr + off);
            uint2 hb = *reinterpret_cast<const uint2*>(g_aggr + (long long)N_NODES * D + off);
            float2 a0 = __half22float2(*reinterpret_cast<__half2*>(&ha.x));
            float2 a1 = __half22float2(*reinterpret_cast<__half2*>(&ha.y));
            float2 b0 = __half22float2(*reinterpret_cast<__half2*>(&hb.x));
            float2 b1 = __half22float2(*reinterpret_cast<__half2*>(&hb.y));
            v = make_float4(a0.x + b0.x, a0.y + b0.y, a1.x + b1.x, a1.y + b1.y);
        }
        *reinterpret_cast<float4*>(sAX + n * 128 + c * 4) = v;
    }
    // --- stage x rows (f32, exact) ---
    for (int i = tid; i < NPB * 16; i += 256) {
        int n = i >> 4, c = i & 15;
        int node = node0 + n;
        float4 v = make_float4(0.f, 0.f, 0.f, 0.f);
        if (node < N_NODES)
            v = *reinterpret_cast<const float4*>(x + (long long)node * D + c * 4);
        *reinterpret_cast<float4*>(sAX + n * 128 + 64 + c * 4) = v;
    }
    __syncthreads();

    int tx = tid & 15;
    int ng = tid >> 4;

    float4 bb = reinterpret_cast<float4*>(sB)[tx];
    ull acc[4][2];
    {
        ull bxy, bzw;
        PACK_F32X2(bxy, bb.x, bb.y);
        PACK_F32X2(bzw, bb.z, bb.w);
#pragma unroll
        for (int n = 0; n < 4; n++) { acc[n][0] = bxy; acc[n][1] = bzw; }
    }

    const float* r0 = sAX + (ng * 4 + 0) * 128;
    const float* r1 = sAX + (ng * 4 + 1) * 128;
    const float* r2 = sAX + (ng * 4 + 2) * 128;
    const float* r3 = sAX + (ng * 4 + 3) * 128;
    const ulonglong2* sW2 = reinterpret_cast<const ulonglong2*>(sW);

#pragma unroll 4
    for (int k0 = 0; k0 < 128; k0 += 4) {
        float4 a0 = *reinterpret_cast<const float4*>(r0 + k0);
        float4 a1 = *reinterpret_cast<const float4*>(r1 + k0);
        float4 a2 = *reinterpret_cast<const float4*>(r2 + k0);
        float4 a3 = *reinterpret_cast<const float4*>(r3 + k0);
        const float* ap0 = reinterpret_cast<const float*>(&a0);
        const float* ap1 = reinterpret_cast<const float*>(&a1);
        const float* ap2 = reinterpret_cast<const float*>(&a2);
        const float* ap3 = reinterpret_cast<const float*>(&a3);
#pragma unroll
        for (int kk = 0; kk < 4; kk++) {
            ulonglong2 w = sW2[(k0 + kk) * 16 + tx];
            ull aa0, aa1, aa2, aa3;
            PACK_F32X2(aa0, ap0[kk], ap0[kk]);
            PACK_F32X2(aa1, ap1[kk], ap1[kk]);
            PACK_F32X2(aa2, ap2[kk], ap2[kk]);
            PACK_F32X2(aa3, ap3[kk], ap3[kk]);
            FMA_F32X2(acc[0][0], aa0, w.x, acc[0][0]);
            FMA_F32X2(acc[0][1], aa0, w.y, acc[0][1]);
            FMA_F32X2(acc[1][0], aa1, w.x, acc[1][0]);
            FMA_F32X2(acc[1][1], aa1, w.y, acc[1][1]);
            FMA_F32X2(acc[2][0], aa2, w.x, acc[2][0]);
            FMA_F32X2(acc[2][1], aa2, w.y, acc[2][1]);
            FMA_F32X2(acc[3][0], aa3, w.x, acc[3][0]);
            FMA_F32X2(acc[3][1], aa3, w.y, acc[3][1]);
        }
    }

#pragma unroll
    for (int n = 0; n < 4; n++) {
        int node = node0 + ng * 4 + n;
        if (node < N_NODES) {
            float4 a;
            UNPACK_F32X2(a.x, a.y, acc[n][0]);
            UNPACK_F32X2(a.z, a.w, acc[n][1]);
            TANH_APPROX(a.x, a.x);
            TANH_APPROX(a.y, a.y);
            TANH_APPROX(a.z, a.z);
            TANH_APPROX(a.w, a.w);
            *reinterpret_cast<float4*>(out + (long long)node * D + tx * 4) = a;
        }
    }
}

// ---------------------------------------------------------------------------
extern "C" void kernel_launch(void* const* d_in, const int* in_sizes, int n_in,
                              void* d_out, int out_size) {
    const float* x  = (const float*)d_in[0];
    const int*   ei = (const int*)d_in[1];
    const float* Wl = (const float*)d_in[2];
    const float* bl = (const float*)d_in[3];
    const float* Wr = (const float*)d_in[4];
    float* out = (float*)d_out;

    static void* aggr_ptr = nullptr;
    static cudaStream_t s2 = nullptr;
    static cudaEvent_t evFork = nullptr, evJoin = nullptr;
    if (s2 == nullptr) {
        cudaGetSymbolAddress(&aggr_ptr, g_aggr);
        cudaStreamCreateWithFlags(&s2, cudaStreamNonBlocking);
        cudaEventCreateWithFlags(&evFork, cudaEventDisableTiming);
        cudaEventCreateWithFlags(&evJoin, cudaEventDisableTiming);
    }

    // 1) memset (copy engine, side stream) overlapped with cvt_x (SMs, main)
    cudaEventRecord(evFork, 0);
    cudaStreamWaitEvent(s2, evFork, 0);
    cudaMemsetAsync(aggr_ptr, 0, (size_t)2 * N_NODES * D * sizeof(__half), s2);
    cudaEventRecord(evJoin, s2);
    cvt_x_kernel<<<(N_NODES * D / 8 + 255) / 256, 256>>>(x);
    cudaStreamWaitEvent((cudaStream_t)0, evJoin, 0);

    // 2) fp16 edge scatter-add: 8 threads/edge, parity-split buffers
    scatter_kernel<<<(N_EDGES * 8 + 255) / 256, 256>>>(ei);

    // 3) fused GEMM + bias + tanh
    const int smem = (128 * 64 + NPB * 128 + 64) * (int)sizeof(float);  // 65792 B
    static bool attr_set = false;
    if (!attr_set) {
        cudaFuncSetAttribute(fused_gemm_kernel,
                             cudaFuncAttributeMaxDynamicSharedMemorySize, smem);
        attr_set = true;
    }
    fused_gemm_kernel<<<(N_NODES + NPB - 1) / NPB, 256, smem>>>(x, Wl, bl, Wr, out);
}

// round 12
// speedup vs baseline: 1.0660x; 1.0660x over previous
#include <cuda_runtime.h>
#include <cuda_fp16.h>
#include <cstdint>

#define N_NODES 100000
#define N_EDGES 1250000
#define D 64
#define NPB 64          // nodes per block in the fused GEMM
#define SAXS 132        // padded sAX row stride (floats): 528B kills 2048B-period conflicts

typedef unsigned long long ull;

#define PACK_F32X2(out, lo, hi) \
    asm("mov.b64 %0, {%1, %2};" : "=l"(out) : "f"(lo), "f"(hi))
#define UNPACK_F32X2(lo, hi, in) \
    asm("mov.b64 {%0, %1}, %2;" : "=f"(lo), "=f"(hi) : "l"(in))
#define FMA_F32X2(d, a, b, c) \
    asm("fma.rn.f32x2 %0, %1, %2, %3;" : "=l"(d) : "l"(a), "l"(b), "l"(c))
#define TANH_APPROX(y, x) \
    asm("tanh.approx.f32 %0, %1;" : "=f"(y) : "f"(x))

// fp16 scratch (static device memory: allowed, no allocation)
__device__ __half g_aggr[N_NODES * D];   // 12.8 MB aggregation buffer
__device__ __half g_xh[N_NODES * D];     // 12.8 MB fp16 copy of x

// ---------------------------------------------------------------------------
// Prepass: x (f32) -> g_xh (fp16). 16 floats (64B) per thread for MLP.
// ---------------------------------------------------------------------------
__global__ void cvt_x_kernel(const float* __restrict__ x) {
    int i = blockIdx.x * blockDim.x + threadIdx.x;   // group of 16 floats
    if (i >= N_NODES * D / 16) return;
    const float4* xp = reinterpret_cast<const float4*>(x) + i * 4;
    float4 v0 = xp[0], v1 = xp[1], v2 = xp[2], v3 = xp[3];
    __half2 h[8];
    h[0] = __float22half2_rn(make_float2(v0.x, v0.y));
    h[1] = __float22half2_rn(make_float2(v0.z, v0.w));
    h[2] = __float22half2_rn(make_float2(v1.x, v1.y));
    h[3] = __float22half2_rn(make_float2(v1.z, v1.w));
    h[4] = __float22half2_rn(make_float2(v2.x, v2.y));
    h[5] = __float22half2_rn(make_float2(v2.z, v2.w));
    h[6] = __float22half2_rn(make_float2(v3.x, v3.y));
    h[7] = __float22half2_rn(make_float2(v3.z, v3.w));
    uint4* op = reinterpret_cast<uint4*>(g_xh) + i * 2;
    op[0] = reinterpret_cast<uint4*>(h)[0];
    op[1] = reinterpret_cast<uint4*>(h)[1];
}

// ---------------------------------------------------------------------------
// Scatter: 8 threads/edge; each loads 8 halves of x_h[src] (one LDG.128) and
// does one red.global.add.noftz.v4.f16x2 into g_aggr[dst] (one RED.128).
// Runtime probe of int64 vs int32 edge_index (ids < 2^31 -> odd words zero).
// ---------------------------------------------------------------------------
__global__ void scatter_kernel(const int* __restrict__ e32) {
    int t = blockIdx.x * blockDim.x + threadIdx.x;
    int e = t >> 3;
    if (e >= N_EDGES) return;
    int c = (t & 7) << 3;   // half offset within row (0,8,...,56)

    bool is64 = (e32[1] == 0) && (e32[3] == 0) && (e32[5] == 0) && (e32[7] == 0);

    int src, dst;
    if (is64) {
        src = e32[2 * e];
        dst = e32[2 * (N_EDGES + e)];
    } else {
        src = e32[e];
        dst = e32[N_EDGES + e];
    }

    uint4 v = *reinterpret_cast<const uint4*>(g_xh + (long long)src * D + c);
    __half* p = g_aggr + (long long)dst * D + c;
    asm volatile("red.global.add.noftz.v4.f16x2 [%0], {%1,%2,%3,%4};"
                 :: "l"(p), "r"(v.x), "r"(v.y), "r"(v.z), "r"(v.w)
                 : "memory");
}

// ---------------------------------------------------------------------------
// Fused GEMM: out = tanh( [aggr | x] @ [W_l ; W_r] + b ) per node.
// aggr read from g_aggr (fp16 -> f32); all math fp32 (packed fma.rn.f32x2).
// Block: 256 threads, NPB=64 nodes; thread (tx, ng) computes cols
// [4tx,4tx+4) of nodes 4ng..4ng+3. sAX rows padded to 132 floats.
// ---------------------------------------------------------------------------
__global__ void fused_gemm_kernel(const float* __restrict__ x,
                                  const float* __restrict__ Wl,
                                  const float* __restrict__ bl,
                                  const float* __restrict__ Wr,
                                  float* __restrict__ out) {
    extern __shared__ float sm[];
    float* sW  = sm;                 // [128][64]: rows 0..63 = W_l, 64..127 = W_r
    float* sAX = sm + 128 * 64;      // [NPB][SAXS]: cols 0..63 aggr, 64..127 x
    float* sB  = sAX + NPB * SAXS;   // [64]

    int tid = threadIdx.x;
    int node0 = blockIdx.x * NPB;

    // --- stage weights ---
    float4* sW4 = reinterpret_cast<float4*>(sW);
    const float4* Wl4 = reinterpret_cast<const float4*>(Wl);
    const float4* Wr4 = reinterpret_cast<const float4*>(Wr);
#pragma unroll
    for (int i = 0; i < 4; i++) {
        int idx = tid + i * 256;
        sW4[idx]        = Wl4[idx];
        sW4[1024 + idx] = Wr4[idx];
    }
    if (tid < 64) sB[tid] = bl[tid];

    // --- stage aggr (fp16 -> f32): NPB nodes * 16 groups of 4 halves ---
    for (int i = tid; i < NPB * 16; i += 256) {
        int n = i >> 4, c = i & 15;
        int node = node0 + n;
        float4 v = make_float4(0.f, 0.f, 0.f, 0.f);
        if (node < N_NODES) {
            uint2 hw = *reinterpret_cast<const uint2*>(g_aggr + (long long)node * D + c * 4);
            float2 f0 = __half22float2(*reinterpret_cast<__half2*>(&hw.x));
            float2 f1 = __half22float2(*reinterpret_cast<__half2*>(&hw.y));
            v = make_float4(f0.x, f0.y, f1.x, f1.y);
        }
        *reinterpret_cast<float4*>(sAX + n * SAXS + c * 4) = v;
    }
    // --- stage x rows (f32, exact) ---
    for (int i = tid; i < NPB * 16; i += 256) {
        int n = i >> 4, c = i & 15;
        int node = node0 + n;
        float4 v = make_float4(0.f, 0.f, 0.f, 0.f);
        if (node < N_NODES)
            v = *reinterpret_cast<const float4*>(x + (long long)node * D + c * 4);
        *reinterpret_cast<float4*>(sAX + n * SAXS + 64 + c * 4) = v;
    }
    __syncthreads();

    int tx = tid & 15;
    int ng = tid >> 4;

    float4 bb = reinterpret_cast<float4*>(sB)[tx];
    ull acc[4][2];
    {
        ull bxy, bzw;
        PACK_F32X2(bxy, bb.x, bb.y);
        PACK_F32X2(bzw, bb.z, bb.w);
#pragma unroll
        for (int n = 0; n < 4; n++) { acc[n][0] = bxy; acc[n][1] = bzw; }
    }

    const float* r0 = sAX + (ng * 4 + 0) * SAXS;
    const float* r1 = sAX + (ng * 4 + 1) * SAXS;
    const float* r2 = sAX + (ng * 4 + 2) * SAXS;
    const float* r3 = sAX + (ng * 4 + 3) * SAXS;
    const ulonglong2* sW2 = reinterpret_cast<const ulonglong2*>(sW);

#pragma unroll 4
    for (int k0 = 0; k0 < 128; k0 += 4) {
        float4 a0 = *reinterpret_cast<const float4*>(r0 + k0);
        float4 a1 = *reinterpret_cast<const float4*>(r1 + k0);
        float4 a2 = *reinterpret_cast<const float4*>(r2 + k0);
        float4 a3 = *reinterpret_cast<const float4*>(r3 + k0);
        const float* ap0 = reinterpret_cast<const float*>(&a0);
        const float* ap1 = reinterpret_cast<const float*>(&a1);
        const float* ap2 = reinterpret_cast<const float*>(&a2);
        const float* ap3 = reinterpret_cast<const float*>(&a3);
#pragma unroll
        for (int kk = 0; kk < 4; kk++) {
            ulonglong2 w = sW2[(k0 + kk) * 16 + tx];
            ull aa0, aa1, aa2, aa3;
            PACK_F32X2(aa0, ap0[kk], ap0[kk]);
            PACK_F32X2(aa1, ap1[kk], ap1[kk]);
            PACK_F32X2(aa2, ap2[kk], ap2[kk]);
            PACK_F32X2(aa3, ap3[kk], ap3[kk]);
            FMA_F32X2(acc[0][0], aa0, w.x, acc[0][0]);
            FMA_F32X2(acc[0][1], aa0, w.y, acc[0][1]);
            FMA_F32X2(acc[1][0], aa1, w.x, acc[1][0]);
            FMA_F32X2(acc[1][1], aa1, w.y, acc[1][1]);
            FMA_F32X2(acc[2][0], aa2, w.x, acc[2][0]);
            FMA_F32X2(acc[2][1], aa2, w.y, acc[2][1]);
            FMA_F32X2(acc[3][0], aa3, w.x, acc[3][0]);
            FMA_F32X2(acc[3][1], aa3, w.y, acc[3][1]);
        }
    }

#pragma unroll
    for (int n = 0; n < 4; n++) {
        int node = node0 + ng * 4 + n;
        if (node < N_NODES) {
            float4 a;
            UNPACK_F32X2(a.x, a.y, acc[n][0]);
            UNPACK_F32X2(a.z, a.w, acc[n][1]);
            TANH_APPROX(a.x, a.x);
            TANH_APPROX(a.y, a.y);
            TANH_APPROX(a.z, a.z);
            TANH_APPROX(a.w, a.w);
            *reinterpret_cast<float4*>(out + (long long)node * D + tx * 4) = a;
        }
    }
}

// ---------------------------------------------------------------------------
extern "C" void kernel_launch(void* const* d_in, const int* in_sizes, int n_in,
                              void* d_out, int out_size) {
    const float* x  = (const float*)d_in[0];
    const int*   ei = (const int*)d_in[1];
    const float* Wl = (const float*)d_in[2];
    const float* bl = (const float*)d_in[3];
    const float* Wr = (const float*)d_in[4];
    float* out = (float*)d_out;

    static void* aggr_ptr = nullptr;
    static cudaStream_t s2 = nullptr;
    static cudaEvent_t evFork = nullptr, evJoin = nullptr;
    if (s2 == nullptr) {
        cudaGetSymbolAddress(&aggr_ptr, g_aggr);
        cudaStreamCreateWithFlags(&s2, cudaStreamNonBlocking);
        cudaEventCreateWithFlags(&evFork, cudaEventDisableTiming);
        cudaEventCreateWithFlags(&evJoin, cudaEventDisableTiming);
    }

    // 1) memset (copy engine, side stream) overlapped with cvt_x (SMs, main)
    cudaEventRecord(evFork, 0);
    cudaStreamWaitEvent(s2, evFork, 0);
    cudaMemsetAsync(aggr_ptr, 0, (size_t)N_NODES * D * sizeof(__half), s2);
    cudaEventRecord(evJoin, s2);
    cvt_x_kernel<<<(N_NODES * D / 16 + 255) / 256, 256>>>(x);
    cudaStreamWaitEvent((cudaStream_t)0, evJoin, 0);

    // 2) fp16 edge scatter-add: 8 threads/edge
    scatter_kernel<<<(N_EDGES * 8 + 255) / 256, 256>>>(ei);

    // 3) fused GEMM + bias + tanh
    const int smem = (128 * 64 + NPB * SAXS + 64) * (int)sizeof(float);  // 66816 B
    static bool attr_set = false;
    if (!attr_set) {
        cudaFuncSetAttribute(fused_gemm_kernel,
                             cudaFuncAttributeMaxDynamicSharedMemorySize, smem);
        attr_set = true;
    }
    fused_gemm_kernel<<<(N_NODES + NPB - 1) / NPB, 256, smem>>>(x, Wl, bl, Wr, out);
}

// round 15
// speedup vs baseline: 1.0844x; 1.0172x over previous
#include <cuda_runtime.h>
#include <cuda_fp16.h>
#include <cstdint>

#define N_NODES 100000
#define N_EDGES 1250000
#define D 64
#define NPB 64          // nodes per block in the fused GEMM
#define SAXS 132        // padded sAX row stride (floats): kills 512B-period bank conflicts

typedef unsigned long long ull;

#define PACK_F32X2(out, lo, hi) \
    asm("mov.b64 %0, {%1, %2};" : "=l"(out) : "f"(lo), "f"(hi))
#define UNPACK_F32X2(lo, hi, in) \
    asm("mov.b64 {%0, %1}, %2;" : "=f"(lo), "=f"(hi) : "l"(in))
#define FMA_F32X2(d, a, b, c) \
    asm("fma.rn.f32x2 %0, %1, %2, %3;" : "=l"(d) : "l"(a), "l"(b), "l"(c))
#define TANH_APPROX(y, x) \
    asm("tanh.approx.f32 %0, %1;" : "=f"(y) : "f"(x))

// fp16 scratch (static device memory: allowed, no allocation)
__device__ __half g_aggr[N_NODES * D];   // 12.8 MB aggregation buffer
__device__ __half g_xh[N_NODES * D];     // 12.8 MB fp16 copy of x

// ---------------------------------------------------------------------------
// Prepass: x (f32) -> g_xh (fp16). 8 floats per thread (R10-measured 8.3us).
// ---------------------------------------------------------------------------
__global__ void cvt_x_kernel(const float* __restrict__ x) {
    int i = blockIdx.x * blockDim.x + threadIdx.x;   // group of 8 floats
    if (i >= N_NODES * D / 8) return;
    const float4* xp = reinterpret_cast<const float4*>(x) + i * 2;
    float4 v0 = xp[0], v1 = xp[1];
    __half2 h[4];
    h[0] = __float22half2_rn(make_float2(v0.x, v0.y));
    h[1] = __float22half2_rn(make_float2(v0.z, v0.w));
    h[2] = __float22half2_rn(make_float2(v1.x, v1.y));
    h[3] = __float22half2_rn(make_float2(v1.z, v1.w));
    *(reinterpret_cast<uint4*>(g_xh) + i) = *reinterpret_cast<uint4*>(h);
}

// ---------------------------------------------------------------------------
// Scatter: 8 threads/edge; each loads 8 halves of x_h[src] (one LDG.128) and
// does one red.global.add.noftz.v4.f16x2 into g_aggr[dst] (one RED.128).
// Runtime probe of int64 vs int32 edge_index (ids < 2^31 -> odd words zero).
// ---------------------------------------------------------------------------
__global__ void scatter_kernel(const int* __restrict__ e32) {
    int t = blockIdx.x * blockDim.x + threadIdx.x;
    int e = t >> 3;
    if (e >= N_EDGES) return;
    int c = (t & 7) << 3;   // half offset within row (0,8,...,56)

    bool is64 = (e32[1] == 0) && (e32[3] == 0) && (e32[5] == 0) && (e32[7] == 0);

    int src, dst;
    if (is64) {
        src = e32[2 * e];
        dst = e32[2 * (N_EDGES + e)];
    } else {
        src = e32[e];
        dst = e32[N_EDGES + e];
    }

    uint4 v = *reinterpret_cast<const uint4*>(g_xh + (long long)src * D + c);
    __half* p = g_aggr + (long long)dst * D + c;
    asm volatile("red.global.add.noftz.v4.f16x2 [%0], {%1,%2,%3,%4};"
                 :: "l"(p), "r"(v.x), "r"(v.y), "r"(v.z), "r"(v.w)
                 : "memory");
}

// ---------------------------------------------------------------------------
// Fused GEMM: out = tanh( [aggr | x] @ [W_l ; W_r] + b ) per node.
// aggr read from g_aggr (fp16 -> f32); all math fp32 (packed fma.rn.f32x2).
// Block: 256 threads, NPB=64 nodes; thread (tx, ng) computes cols
// [4tx,4tx+4) of nodes 4ng..4ng+3. sAX rows padded to SAXS floats.
// ---------------------------------------------------------------------------
__global__ void fused_gemm_kernel(const float* __restrict__ x,
                                  const float* __restrict__ Wl,
                                  const float* __restrict__ bl,
                                  const float* __restrict__ Wr,
                                  float* __restrict__ out) {
    extern __shared__ float sm[];
    float* sW  = sm;                 // [128][64]: rows 0..63 = W_l, 64..127 = W_r
    float* sAX = sm + 128 * 64;      // [NPB][SAXS]: cols 0..63 aggr, 64..127 x
    float* sB  = sAX + NPB * SAXS;   // [64]

    int tid = threadIdx.x;
    int node0 = blockIdx.x * NPB;

    // --- stage weights ---
    float4* sW4 = reinterpret_cast<float4*>(sW);
    const float4* Wl4 = reinterpret_cast<const float4*>(Wl);
    const float4* Wr4 = reinterpret_cast<const float4*>(Wr);
#pragma unroll
    for (int i = 0; i < 4; i++) {
        int idx = tid + i * 256;
        sW4[idx]        = Wl4[idx];
        sW4[1024 + idx] = Wr4[idx];
    }
    if (tid < 64) sB[tid] = bl[tid];

    // --- stage aggr (fp16 -> f32): NPB nodes * 16 groups of 4 halves ---
    for (int i = tid; i < NPB * 16; i += 256) {
        int n = i >> 4, c = i & 15;
        int node = node0 + n;
        float4 v = make_float4(0.f, 0.f, 0.f, 0.f);
        if (node < N_NODES) {
            uint2 hw = *reinterpret_cast<const uint2*>(g_aggr + (long long)node * D + c * 4);
            float2 f0 = __half22float2(*reinterpret_cast<__half2*>(&hw.x));
            float2 f1 = __half22float2(*reinterpret_cast<__half2*>(&hw.y));
            v = make_float4(f0.x, f0.y, f1.x, f1.y);
        }
        *reinterpret_cast<float4*>(sAX + n * SAXS + c * 4) = v;
    }
    // --- stage x rows (f32, exact) ---
    for (int i = tid; i < NPB * 16; i += 256) {
        int n = i >> 4, c = i & 15;
        int node = node0 + n;
        float4 v = make_float4(0.f, 0.f, 0.f, 0.f);
        if (node < N_NODES)
            v = *reinterpret_cast<const float4*>(x + (long long)node * D + c * 4);
        *reinterpret_cast<float4*>(sAX + n * SAXS + 64 + c * 4) = v;
    }
    __syncthreads();

    int tx = tid & 15;
    int ng = tid >> 4;

    float4 bb = reinterpret_cast<float4*>(sB)[tx];
    ull acc[4][2];
    {
        ull bxy, bzw;
        PACK_F32X2(bxy, bb.x, bb.y);
        PACK_F32X2(bzw, bb.z, bb.w);
#pragma unroll
        for (int n = 0; n < 4; n++) { acc[n][0] = bxy; acc[n][1] = bzw; }
    }

    const float* r0 = sAX + (ng * 4 + 0) * SAXS;
    const float* r1 = sAX + (ng * 4 + 1) * SAXS;
    const float* r2 = sAX + (ng * 4 + 2) * SAXS;
    const float* r3 = sAX + (ng * 4 + 3) * SAXS;
    const ulonglong2* sW2 = reinterpret_cast<const ulonglong2*>(sW);

#pragma unroll 4
    for (int k0 = 0; k0 < 128; k0 += 4) {
        float4 a0 = *reinterpret_cast<const float4*>(r0 + k0);
        float4 a1 = *reinterpret_cast<const float4*>(r1 + k0);
        float4 a2 = *reinterpret_cast<const float4*>(r2 + k0);
        float4 a3 = *reinterpret_cast<const float4*>(r3 + k0);
        const float* ap0 = reinterpret_cast<const float*>(&a0);
        const float* ap1 = reinterpret_cast<const float*>(&a1);
        const float* ap2 = reinterpret_cast<const float*>(&a2);
        const float* ap3 = reinterpret_cast<const float*>(&a3);
#pragma unroll
        for (int kk = 0; kk < 4; kk++) {
            ulonglong2 w = sW2[(k0 + kk) * 16 + tx];
            ull aa0, aa1, aa2, aa3;
            PACK_F32X2(aa0, ap0[kk], ap0[kk]);
            PACK_F32X2(aa1, ap1[kk], ap1[kk]);
            PACK_F32X2(aa2, ap2[kk], ap2[kk]);
            PACK_F32X2(aa3, ap3[kk], ap3[kk]);
            FMA_F32X2(acc[0][0], aa0, w.x, acc[0][0]);
            FMA_F32X2(acc[0][1], aa0, w.y, acc[0][1]);
            FMA_F32X2(acc[1][0], aa1, w.x, acc[1][0]);
            FMA_F32X2(acc[1][1], aa1, w.y, acc[1][1]);
            FMA_F32X2(acc[2][0], aa2, w.x, acc[2][0]);
            FMA_F32X2(acc[2][1], aa2, w.y, acc[2][1]);
            FMA_F32X2(acc[3][0], aa3, w.x, acc[3][0]);
            FMA_F32X2(acc[3][1], aa3, w.y, acc[3][1]);
        }
    }

#pragma unroll
    for (int n = 0; n < 4; n++) {
        int node = node0 + ng * 4 + n;
        if (node < N_NODES) {
            float4 a;
            UNPACK_F32X2(a.x, a.y, acc[n][0]);
            UNPACK_F32X2(a.z, a.w, acc[n][1]);
            TANH_APPROX(a.x, a.x);
            TANH_APPROX(a.y, a.y);
            TANH_APPROX(a.z, a.z);
            TANH_APPROX(a.w, a.w);
            *reinterpret_cast<float4*>(out + (long long)node * D + tx * 4) = a;
        }
    }
}

// ---------------------------------------------------------------------------
extern "C" void kernel_launch(void* const* d_in, const int* in_sizes, int n_in,
                              void* d_out, int out_size) {
    const float* x  = (const float*)d_in[0];
    const int*   ei = (const int*)d_in[1];
    const float* Wl = (const float*)d_in[2];
    const float* bl = (const float*)d_in[3];
    const float* Wr = (const float*)d_in[4];
    float* out = (float*)d_out;

    static void* aggr_ptr = nullptr;
    if (aggr_ptr == nullptr) cudaGetSymbolAddress(&aggr_ptr, g_aggr);

    // 1) zero fp16 aggr buffer (serial main-stream memset node: fast path)
    //    + fp16 prepass of x
    cudaMemsetAsync(aggr_ptr, 0, (size_t)N_NODES * D * sizeof(__half));
    cvt_x_kernel<<<(N_NODES * D / 8 + 255) / 256, 256>>>(x);

    // 2) fp16 edge scatter-add: 8 threads/edge
    scatter_kernel<<<(N_EDGES * 8 + 255) / 256, 256>>>(ei);

    // 3) fused GEMM + bias + tanh
    const int smem = (128 * 64 + NPB * SAXS + 64) * (int)sizeof(float);  // 66816 B
    static bool attr_set = false;
    if (!attr_set) {
        cudaFuncSetAttribute(fused_gemm_kernel,
                             cudaFuncAttributeMaxDynamicSharedMemorySize, smem);
        attr_set = true;
    }
    fused_gemm_kernel<<<(N_NODES + NPB - 1) / NPB, 256, smem>>>(x, Wl, bl, Wr, out);
}

// round 16
// speedup vs baseline: 1.2127x; 1.1184x over previous
#include <cuda_runtime.h>
#include <cuda_fp16.h>
#include <cstdint>

#define N_NODES 100000
#define N_EDGES 1250000
#define D 64
#define NPB 128         // nodes per block in the fused GEMM
#define SAXS 132        // padded sAX row stride (floats); 132 mod 32 = 4 banks/row

typedef unsigned long long ull;

#define PACK_F32X2(out, lo, hi) \
    asm("mov.b64 %0, {%1, %2};" : "=l"(out) : "f"(lo), "f"(hi))
#define UNPACK_F32X2(lo, hi, in) \
    asm("mov.b64 {%0, %1}, %2;" : "=f"(lo), "=f"(hi) : "l"(in))
#define FMA_F32X2(d, a, b, c) \
    asm("fma.rn.f32x2 %0, %1, %2, %3;" : "=l"(d) : "l"(a), "l"(b), "l"(c))
#define TANH_APPROX(y, x) \
    asm("tanh.approx.f32 %0, %1;" : "=f"(y) : "f"(x))

// fp16 scratch (static device memory: allowed, no allocation)
__device__ __half g_aggr[N_NODES * D];   // 12.8 MB aggregation buffer
__device__ __half g_xh[N_NODES * D];     // 12.8 MB fp16 copy of x

// ---------------------------------------------------------------------------
// Prepass: x (f32) -> g_xh (fp16). 8 floats per thread (measured ~8us).
// ---------------------------------------------------------------------------
__global__ void cvt_x_kernel(const float* __restrict__ x) {
    int i = blockIdx.x * blockDim.x + threadIdx.x;   // group of 8 floats
    if (i >= N_NODES * D / 8) return;
    const float4* xp = reinterpret_cast<const float4*>(x) + i * 2;
    float4 v0 = xp[0], v1 = xp[1];
    __half2 h[4];
    h[0] = __float22half2_rn(make_float2(v0.x, v0.y));
    h[1] = __float22half2_rn(make_float2(v0.z, v0.w));
    h[2] = __float22half2_rn(make_float2(v1.x, v1.y));
    h[3] = __float22half2_rn(make_float2(v1.z, v1.w));
    *(reinterpret_cast<uint4*>(g_xh) + i) = *reinterpret_cast<uint4*>(h);
}

// ---------------------------------------------------------------------------
// Scatter: 8 threads/edge; each loads 8 halves of x_h[src] (one LDG.128) and
// does one red.global.add.noftz.v4.f16x2 into g_aggr[dst] (one RED.128).
// Runtime probe of int64 vs int32 edge_index (ids < 2^31 -> odd words zero).
// ---------------------------------------------------------------------------
__global__ void scatter_kernel(const int* __restrict__ e32) {
    int t = blockIdx.x * blockDim.x + threadIdx.x;
    int e = t >> 3;
    if (e >= N_EDGES) return;
    int c = (t & 7) << 3;   // half offset within row (0,8,...,56)

    bool is64 = (e32[1] == 0) && (e32[3] == 0) && (e32[5] == 0) && (e32[7] == 0);

    int src, dst;
    if (is64) {
        src = e32[2 * e];
        dst = e32[2 * (N_EDGES + e)];
    } else {
        src = e32[e];
        dst = e32[N_EDGES + e];
    }

    uint4 v = *reinterpret_cast<const uint4*>(g_xh + (long long)src * D + c);
    __half* p = g_aggr + (long long)dst * D + c;
    asm volatile("red.global.add.noftz.v4.f16x2 [%0], {%1,%2,%3,%4};"
                 :: "l"(p), "r"(v.x), "r"(v.y), "r"(v.z), "r"(v.w)
                 : "memory");
}

// ---------------------------------------------------------------------------
// Fused GEMM: out = tanh( [aggr | x] @ [W_l ; W_r] + b ) per node.
// Thread (tx, ng): cols [4tx,4tx+4) of rows ng+16j, j=0..7 (8 nodes).
// a-loads broadcast within tx-group; adjacent ng rows 4 banks apart.
// ---------------------------------------------------------------------------
__global__ void __launch_bounds__(256, 2)
fused_gemm_kernel(const float* __restrict__ x,
                  const float* __restrict__ Wl,
                  const float* __restrict__ bl,
                  const float* __restrict__ Wr,
                  float* __restrict__ out) {
    extern __shared__ float sm[];
    float* sW  = sm;                 // [128][64]: rows 0..63 = W_l, 64..127 = W_r
    float* sAX = sm + 128 * 64;      // [NPB][SAXS]: cols 0..63 aggr, 64..127 x
    float* sB  = sAX + NPB * SAXS;   // [64]

    int tid = threadIdx.x;
    int node0 = blockIdx.x * NPB;

    // --- stage weights ---
    float4* sW4 = reinterpret_cast<float4*>(sW);
    const float4* Wl4 = reinterpret_cast<const float4*>(Wl);
    const float4* Wr4 = reinterpret_cast<const float4*>(Wr);
#pragma unroll
    for (int i = 0; i < 4; i++) {
        int idx = tid + i * 256;
        sW4[idx]        = Wl4[idx];
        sW4[1024 + idx] = Wr4[idx];
    }
    if (tid < 64) sB[tid] = bl[tid];

    // --- stage aggr (fp16 -> f32): NPB nodes * 16 groups of 4 halves ---
#pragma unroll
    for (int i = tid; i < NPB * 16; i += 256) {
        int n = i >> 4, c = i & 15;
        int node = node0 + n;
        float4 v = make_float4(0.f, 0.f, 0.f, 0.f);
        if (node < N_NODES) {
            uint2 hw = *reinterpret_cast<const uint2*>(g_aggr + (long long)node * D + c * 4);
            float2 f0 = __half22float2(*reinterpret_cast<__half2*>(&hw.x));
            float2 f1 = __half22float2(*reinterpret_cast<__half2*>(&hw.y));
            v = make_float4(f0.x, f0.y, f1.x, f1.y);
        }
        *reinterpret_cast<float4*>(sAX + n * SAXS + c * 4) = v;
    }
    // --- stage x rows (f32, exact) ---
#pragma unroll
    for (int i = tid; i < NPB * 16; i += 256) {
        int n = i >> 4, c = i & 15;
        int node = node0 + n;
        float4 v = make_float4(0.f, 0.f, 0.f, 0.f);
        if (node < N_NODES)
            v = *reinterpret_cast<const float4*>(x + (long long)node * D + c * 4);
        *reinterpret_cast<float4*>(sAX + n * SAXS + 64 + c * 4) = v;
    }
    __syncthreads();

    int tx = tid & 15;   // 16 col-groups * 4 cols = 64 cols
    int ng = tid >> 4;   // 16 row-groups; rows = ng + 16j

    float4 bb = reinterpret_cast<float4*>(sB)[tx];
    ull acc[8][2];
    {
        ull bxy, bzw;
        PACK_F32X2(bxy, bb.x, bb.y);
        PACK_F32X2(bzw, bb.z, bb.w);
#pragma unroll
        for (int j = 0; j < 8; j++) { acc[j][0] = bxy; acc[j][1] = bzw; }
    }

    const float* rbase = sAX + ng * SAXS;   // row ng; row ng+16j at +16j*SAXS
    const ulonglong2* sW2 = reinterpret_cast<const ulonglong2*>(sW);

#pragma unroll 2
    for (int k0 = 0; k0 < 128; k0 += 4) {
        float4 a[8];
#pragma unroll
        for (int j = 0; j < 8; j++)
            a[j] = *reinterpret_cast<const float4*>(rbase + j * 16 * SAXS + k0);
        const float* ap = reinterpret_cast<const float*>(a);
#pragma unroll
        for (int kk = 0; kk < 4; kk++) {
            ulonglong2 w = sW2[(k0 + kk) * 16 + tx];
#pragma unroll
            for (int j = 0; j < 8; j++) {
                ull aa;
                PACK_F32X2(aa, ap[j * 4 + kk], ap[j * 4 + kk]);
                FMA_F32X2(acc[j][0], aa, w.x, acc[j][0]);
                FMA_F32X2(acc[j][1], aa, w.y, acc[j][1]);
            }
        }
    }

#pragma unroll
    for (int j = 0; j < 8; j++) {
        int node = node0 + ng + 16 * j;
        if (node < N_NODES) {
            float4 o;
            UNPACK_F32X2(o.x, o.y, acc[j][0]);
            UNPACK_F32X2(o.z, o.w, acc[j][1]);
            TANH_APPROX(o.x, o.x);
            TANH_APPROX(o.y, o.y);
            TANH_APPROX(o.z, o.z);
            TANH_APPROX(o.w, o.w);
            *reinterpret_cast<float4*>(out + (long long)node * D + tx * 4) = o;
        }
    }
}

// ---------------------------------------------------------------------------
extern "C" void kernel_launch(void* const* d_in, const int* in_sizes, int n_in,
                              void* d_out, int out_size) {
    const float* x  = (const float*)d_in[0];
    const int*   ei = (const int*)d_in[1];
    const float* Wl = (const float*)d_in[2];
    const float* bl = (const float*)d_in[3];
    const float* Wr = (const float*)d_in[4];
    float* out = (float*)d_out;

    static void* aggr_ptr = nullptr;
    if (aggr_ptr == nullptr) cudaGetSymbolAddress(&aggr_ptr, g_aggr);

    // 1) zero fp16 aggr buffer + fp16 prepass of x
    cudaMemsetAsync(aggr_ptr, 0, (size_t)N_NODES * D * sizeof(__half));
    cvt_x_kernel<<<(N_NODES * D / 8 + 255) / 256, 256>>>(x);

    // 2) fp16 edge scatter-add: 8 threads/edge
    scatter_kernel<<<(N_EDGES * 8 + 255) / 256, 256>>>(ei);

    // 3) fused GEMM + bias + tanh
    const int smem = (128 * 64 + NPB * SAXS + 64) * (int)sizeof(float);  // 100608 B
    static bool attr_set = false;
    if (!attr_set) {
        cudaFuncSetAttribute(fused_gemm_kernel,
                             cudaFuncAttributeMaxDynamicSharedMemorySize, smem);
        attr_set = true;
    }
    fused_gemm_kernel<<<(N_NODES + NPB - 1) / NPB, 256, smem>>>(x, Wl, bl, Wr, out);
}